// round 5
// baseline (speedup 1.0000x reference)
#include <cuda_runtime.h>
#include <cuda_bf16.h>
#include <cub/cub.cuh>
#include <math.h>
#include <stdint.h>

#define NENT 512
#define DIM  768
#define HID  256
#define NT   16
#define NN   (NENT * NENT)
#define TI 8
#define TJ 16
#define PAD 65536           // candidate sort capacity
#define GW 2048             // greedy window (keys)

// ---------------- static device scratch (no allocs allowed) ----------------
__device__ float g_G[NENT * 6 * HID];   // [i][ s_i+b | c_i+b | d_i+b | s_j | c_j | d_j ]
__device__ float g_GTc[HID * NENT];     // transposed c_j block: [dim][entity]
__device__ float g_stats[NENT * 4];     // per entity: S1c, Q1c, S2c, Q2c
__device__ float g_dotc[NENT * NENT];   // hi_c . hj_c
__device__ unsigned long long g_ckeys[PAD];
__device__ unsigned long long g_ckeys_s[PAD];
__device__ int g_ncand;
__device__ unsigned char g_sort_tmp[16u << 20];

// ---------------------------------------------------------------------------
__global__ void clear_kernel() {
    int tid = blockIdx.x * blockDim.x + threadIdx.x;
    for (int k = tid; k < PAD; k += gridDim.x * blockDim.x) g_ckeys[k] = 0ull;
    if (tid == 0) g_ncand = 0;
}

// ---------------------------------------------------------------------------
// Kernel 1: six fused projections (unchanged — feeds score path, keep fp32).
// ---------------------------------------------------------------------------
__global__ void __launch_bounds__(256) gemm6_kernel(
    const float* __restrict__ E,
    const float* __restrict__ sW1, const float* __restrict__ cW1, const float* __restrict__ dW1,
    const float* __restrict__ sb1, const float* __restrict__ cb1, const float* __restrict__ db1)
{
    __shared__ float  As[64][17];
    __shared__ float4 Bs[16 * 16];

    int z = blockIdx.z;
    const float* W = (z % 3 == 0) ? sW1 : (z % 3 == 1) ? cW1 : dW1;
    const float* bias = nullptr;
    if (z == 0) bias = sb1; else if (z == 1) bias = cb1; else if (z == 2) bias = db1;
    int rowoff  = (z < 3) ? 0 : DIM;
    int colbase = z * HID;

    int m0 = blockIdx.y * 64;
    int n0 = blockIdx.x * 64;
    int tid = threadIdx.x;
    int tx = tid & 15, ty = tid >> 4;
    int lrow = tid >> 2, lkq = tid & 3;
    int lk   = tid >> 4, lnq = tid & 15;

    float acc[4][4] = {};

    for (int k0 = 0; k0 < DIM; k0 += 16) {
        __syncthreads();
        float4 av = *(const float4*)(E + (size_t)(m0 + lrow) * DIM + k0 + lkq * 4);
        As[lrow][lkq * 4 + 0] = av.x;
        As[lrow][lkq * 4 + 1] = av.y;
        As[lrow][lkq * 4 + 2] = av.z;
        As[lrow][lkq * 4 + 3] = av.w;
        Bs[lk * 16 + lnq] = *(const float4*)(W + (size_t)(rowoff + k0 + lk) * HID + n0 + lnq * 4);
        __syncthreads();
        #pragma unroll
        for (int k = 0; k < 16; k++) {
            float a0 = As[ty * 4 + 0][k];
            float a1 = As[ty * 4 + 1][k];
            float a2 = As[ty * 4 + 2][k];
            float a3 = As[ty * 4 + 3][k];
            float4 b = Bs[k * 16 + tx];
            acc[0][0] = fmaf(a0, b.x, acc[0][0]); acc[0][1] = fmaf(a0, b.y, acc[0][1]);
            acc[0][2] = fmaf(a0, b.z, acc[0][2]); acc[0][3] = fmaf(a0, b.w, acc[0][3]);
            acc[1][0] = fmaf(a1, b.x, acc[1][0]); acc[1][1] = fmaf(a1, b.y, acc[1][1]);
            acc[1][2] = fmaf(a1, b.z, acc[1][2]); acc[1][3] = fmaf(a1, b.w, acc[1][3]);
            acc[2][0] = fmaf(a2, b.x, acc[2][0]); acc[2][1] = fmaf(a2, b.y, acc[2][1]);
            acc[2][2] = fmaf(a2, b.z, acc[2][2]); acc[2][3] = fmaf(a2, b.w, acc[2][3]);
            acc[3][0] = fmaf(a3, b.x, acc[3][0]); acc[3][1] = fmaf(a3, b.y, acc[3][1]);
            acc[3][2] = fmaf(a3, b.z, acc[3][2]); acc[3][3] = fmaf(a3, b.w, acc[3][3]);
        }
    }

    #pragma unroll
    for (int u = 0; u < 4; u++) {
        int gr = m0 + ty * 4 + u;
        int gc = n0 + tx * 4;
        float4 o;
        o.x = acc[u][0]; o.y = acc[u][1]; o.z = acc[u][2]; o.w = acc[u][3];
        if (bias) { o.x += bias[gc]; o.y += bias[gc + 1]; o.z += bias[gc + 2]; o.w += bias[gc + 3]; }
        *(float4*)(g_G + (size_t)gr * (6 * HID) + colbase + gc) = o;
    }
}

// ---------------------------------------------------------------------------
__device__ __forceinline__ float warpsum(float v) {
    v += __shfl_xor_sync(0xffffffffu, v, 16);
    v += __shfl_xor_sync(0xffffffffu, v, 8);
    v += __shfl_xor_sync(0xffffffffu, v, 4);
    v += __shfl_xor_sync(0xffffffffu, v, 2);
    v += __shfl_xor_sync(0xffffffffu, v, 1);
    return v;
}

// exact (libdevice) — score path ONLY
__device__ __forceinline__ float gelu_exact(float x) {
    return 0.5f * x * (1.0f + erff(x * 0.70710678118654752440f));
}

// Abramowitz-Stegun 7.1.26: |err| <= ~1.6e-7 abs. For value-only outputs.
__device__ __forceinline__ float erf_fast(float x) {
    float a = fabsf(x);
    float t = __frcp_rn(fmaf(0.3275911f, a, 1.0f));
    float p = fmaf(1.061405429f, t, -1.453152027f);
    p = fmaf(p, t, 1.421413741f);
    p = fmaf(p, t, -0.284496736f);
    p = fmaf(p, t, 0.254829592f);
    p = p * t;
    float e = __expf(-a * a);
    float r = fmaf(-p, e, 1.0f);
    return copysignf(r, x);
}

__device__ __forceinline__ float gelu_fast(float x) {
    return 0.5f * x * (1.0f + erf_fast(x * 0.70710678118654752440f));
}

// ---------------------------------------------------------------------------
// prep: transpose c_j into g_GTc + per-entity (sum, sumsq) stats.
// ---------------------------------------------------------------------------
__global__ void __launch_bounds__(256) prep_kernel() {
    int b = blockIdx.x;
    int tid = threadIdx.x;
    if (b < 128) {
        __shared__ float t[32][33];
        int e0 = (b & 15) * 32;
        int d0 = (b >> 4) * 32;
        int tx = tid & 31, ty = tid >> 5;
        #pragma unroll
        for (int r = 0; r < 4; r++) {
            int row = ty + r * 8;
            t[row][tx] = g_G[(size_t)(e0 + row) * 1536 + 1024 + d0 + tx];
        }
        __syncthreads();
        #pragma unroll
        for (int r = 0; r < 4; r++) {
            int row = ty + r * 8;
            g_GTc[(size_t)(d0 + row) * NENT + e0 + tx] = t[tx][row];
        }
    } else {
        int warp = tid >> 5, lane = tid & 31;
        int e = (b - 128) * 8 + warp;
        const float* gr = g_G + (size_t)e * 1536;
        float s1 = 0.f, q1 = 0.f, s2 = 0.f, q2 = 0.f;
        #pragma unroll
        for (int q = 0; q < 8; q++) {
            float a = gr[256 + lane * 8 + q];
            float c = gr[1024 + lane * 8 + q];
            s1 += a; q1 = fmaf(a, a, q1);
            s2 += c; q2 = fmaf(c, c, q2);
        }
        s1 = warpsum(s1); q1 = warpsum(q1); s2 = warpsum(s2); q2 = warpsum(q2);
        if (lane == 0) {
            float4 o; o.x = s1; o.y = q1; o.z = s2; o.w = q2;
            *(float4*)(g_stats + e * 4) = o;
        }
    }
}

// ---------------------------------------------------------------------------
// dotc[i][j] = hi_c[i] . hj_c[j]
// ---------------------------------------------------------------------------
__global__ void __launch_bounds__(256) dotc_kernel() {
    __shared__ float As[64][17];
    __shared__ float Bs2[64][17];

    int m0 = blockIdx.y * 64;
    int n0 = blockIdx.x * 64;
    int tid = threadIdx.x;
    int tx = tid & 15, ty = tid >> 4;
    int lrow = tid >> 2, lkq = tid & 3;

    float acc[4][4] = {};

    for (int k0 = 0; k0 < HID; k0 += 16) {
        __syncthreads();
        {
            float4 a = *(const float4*)(g_G + (size_t)(m0 + lrow) * 1536 + 256 + k0 + lkq * 4);
            As[lrow][lkq * 4 + 0] = a.x; As[lrow][lkq * 4 + 1] = a.y;
            As[lrow][lkq * 4 + 2] = a.z; As[lrow][lkq * 4 + 3] = a.w;
            float4 c = *(const float4*)(g_G + (size_t)(n0 + lrow) * 1536 + 1024 + k0 + lkq * 4);
            Bs2[lrow][lkq * 4 + 0] = c.x; Bs2[lrow][lkq * 4 + 1] = c.y;
            Bs2[lrow][lkq * 4 + 2] = c.z; Bs2[lrow][lkq * 4 + 3] = c.w;
        }
        __syncthreads();
        #pragma unroll
        for (int k = 0; k < 16; k++) {
            float a0 = As[ty * 4 + 0][k], a1 = As[ty * 4 + 1][k];
            float a2 = As[ty * 4 + 2][k], a3 = As[ty * 4 + 3][k];
            float b0 = Bs2[tx * 4 + 0][k], b1 = Bs2[tx * 4 + 1][k];
            float b2 = Bs2[tx * 4 + 2][k], b3 = Bs2[tx * 4 + 3][k];
            acc[0][0] = fmaf(a0, b0, acc[0][0]); acc[0][1] = fmaf(a0, b1, acc[0][1]);
            acc[0][2] = fmaf(a0, b2, acc[0][2]); acc[0][3] = fmaf(a0, b3, acc[0][3]);
            acc[1][0] = fmaf(a1, b0, acc[1][0]); acc[1][1] = fmaf(a1, b1, acc[1][1]);
            acc[1][2] = fmaf(a1, b2, acc[1][2]); acc[1][3] = fmaf(a1, b3, acc[1][3]);
            acc[2][0] = fmaf(a2, b0, acc[2][0]); acc[2][1] = fmaf(a2, b1, acc[2][1]);
            acc[2][2] = fmaf(a2, b2, acc[2][2]); acc[2][3] = fmaf(a2, b3, acc[2][3]);
            acc[3][0] = fmaf(a3, b0, acc[3][0]); acc[3][1] = fmaf(a3, b1, acc[3][1]);
            acc[3][2] = fmaf(a3, b2, acc[3][2]); acc[3][3] = fmaf(a3, b3, acc[3][3]);
        }
    }
    #pragma unroll
    for (int u = 0; u < 4; u++) {
        float4 o; o.x = acc[u][0]; o.y = acc[u][1]; o.z = acc[u][2]; o.w = acc[u][3];
        *(float4*)(g_dotc + (size_t)(m0 + ty * 4 + u) * NENT + n0 + tx * 4) = o;
    }
}

// ---------------------------------------------------------------------------
// pair_a: s + d heads. s-head math bit-identical to R2/R3/R4 (score path).
// d-head + dir sigmoid use fast approximations (value-only outputs).
// ---------------------------------------------------------------------------
__global__ void __launch_bounds__(256) paira_kernel(
    const float* __restrict__ sW2, const float* __restrict__ sb2,
    const float* __restrict__ s_g, const float* __restrict__ s_b,
    const float* __restrict__ dW2, const float* __restrict__ db2,
    const int* __restrict__ ebatch,
    float* __restrict__ out, float* __restrict__ selout)
{
    extern __shared__ float sh[];
    float* sh_hj  = sh;                       // [2][TJ][256]  (s_j, d_j)
    float* sh_sg  = sh + 2 * TJ * 256;        // 256
    float* sh_sb  = sh_sg + 256;
    int*   sh_jb  = (int*)(sh_sb + 256);      // 16

    int i0 = blockIdx.y * TI, j0 = blockIdx.x * TJ;
    int tid = threadIdx.x, warp = tid >> 5, lane = tid & 31;

    for (int v = tid; v < 2 * TJ * 64; v += 256) {
        int h = v / (TJ * 64); int rem = v % (TJ * 64);
        int jj = rem / 64; int c4 = rem % 64;
        float4 val = *(const float4*)(g_G + (size_t)(j0 + jj) * 1536 + (3 + 2 * h) * 256 + c4 * 4);
        *(float4*)(sh_hj + ((h * TJ + jj) * 256) + c4 * 4) = val;
    }
    { int c = tid; sh_sg[c] = s_g[c]; sh_sb[c] = s_b[c]; }
    if (tid < 16) sh_jb[tid] = ebatch[j0 + tid];
    __syncthreads();

    int i = i0 + warp;
    int d0 = lane * 8;

    float his[8], hid_[8];
    {
        const float* gr = g_G + (size_t)i * 1536;
        #pragma unroll
        for (int q = 0; q < 8; q++) {
            his[q]  = gr[d0 + q];
            hid_[q] = gr[512 + d0 + q];
        }
    }
    float s2[8], d2v[8];
    #pragma unroll
    for (int q = 0; q < 8; q++) { s2[q] = sW2[d0 + q]; d2v[q] = dW2[d0 + q]; }

    float sbias2 = sb2[0], dbias2 = db2[0];
    int bi = ebatch[i];
    const float inv256 = 1.0f / 256.0f;

    for (int jj = 0; jj < TJ; jj++) {
        int j = j0 + jj;
        float x[8];

        // -------- s head: BIT-IDENTICAL sequence (gelu_exact, expf sigmoid) --------
        const float* hj = sh_hj + (0 * TJ + jj) * 256 + d0;
        float ps = 0.f;
        #pragma unroll
        for (int q = 0; q < 8; q++) { x[q] = his[q] + hj[q]; ps += x[q]; }
        float m = warpsum(ps) * inv256;
        float pv = 0.f;
        #pragma unroll
        for (int q = 0; q < 8; q++) { float dd = x[q] - m; pv = fmaf(dd, dd, pv); }
        float rs = rsqrtf(warpsum(pv) * inv256 + 1e-5f);
        float acc = 0.f;
        #pragma unroll
        for (int q = 0; q < 8; q++) {
            float hn = (x[q] - m) * rs * sh_sg[d0 + q] + sh_sb[d0 + q];
            acc = fmaf(gelu_exact(hn), s2[q], acc);
        }
        acc = warpsum(acc);
        float score = 1.0f / (1.0f + expf(-(acc + sbias2)));

        // -------- d head: fast approximations (value-only output) --------
        const float* hjd = sh_hj + (1 * TJ + jj) * 256 + d0;
        float acc2 = 0.f;
        #pragma unroll
        for (int q = 0; q < 8; q++) {
            float xx = hid_[q] + hjd[q];
            acc2 = fmaf(gelu_fast(xx), d2v[q], acc2);
        }
        acc2 = warpsum(acc2);
        float dir = __frcp_rn(1.0f + __expf(-(acc2 + dbias2)));

        if (lane == 0) {
            size_t pidx = (size_t)i * NENT + j;
            float* orow = out + pidx * 18;
            orow[0]  = score;
            orow[17] = dir;
            selout[pidx] = 0.0f;
            int cand = (bi == sh_jb[jj]) && (i != j) && (score >= 0.5f);
            if (cand) {
                int pos = atomicAdd(&g_ncand, 1);
                if (pos < PAD) {
                    unsigned bits = __float_as_uint(score);
                    unsigned long long key =
                        ((unsigned long long)(bits - 0x3F000000u) << 18) |
                        (unsigned long long)((~(unsigned)pidx) & 0x3FFFFu);
                    g_ckeys[pos] = key;
                }
            }
        }
    }
}

// ---------------------------------------------------------------------------
// pair_c: classifier head, thread-per-pair, fast gelu. Split into half-grids
// (i_off) so both profile slots 4 and 5 show this kernel.
// ---------------------------------------------------------------------------
__global__ void __launch_bounds__(256) pairc_kernel(
    const float* __restrict__ cW2, const float* __restrict__ cb2,
    const float* __restrict__ c_g, const float* __restrict__ c_b,
    float* __restrict__ out, int i_off)
{
    __shared__ float sh_hic[256], sh_g[256], sh_b[256], sh_cb2v[16];
    __shared__ float sh_c2[256 * 16];

    int tid = threadIdx.x;
    int i = blockIdx.y + i_off;
    int j = blockIdx.x * 256 + tid;

    sh_hic[tid] = g_G[(size_t)i * 1536 + 256 + tid];
    sh_g[tid] = c_g[tid];
    sh_b[tid] = c_b[tid];
    for (int k = tid; k < 1024; k += 256)
        ((float4*)sh_c2)[k] = ((const float4*)cW2)[k];
    if (tid < 16) sh_cb2v[tid] = cb2[tid];
    __syncthreads();

    const float inv256 = 1.0f / 256.0f;
    float4 stj = *(const float4*)(g_stats + j * 4);
    float S1 = g_stats[i * 4 + 0];
    float Q1 = g_stats[i * 4 + 1];
    float dot = g_dotc[(size_t)i * NENT + j];
    float m = (S1 + stj.z) * inv256;
    float var = fmaf(-m, m, (Q1 + 2.0f * dot + stj.w) * inv256);
    float rs = rsqrtf(var + 1e-5f);

    float v[16];
    #pragma unroll
    for (int t = 0; t < 16; t++) v[t] = 0.f;

    #pragma unroll 4
    for (int d = 0; d < 256; d++) {
        float x = sh_hic[d] + g_GTc[(size_t)d * NENT + j];
        float t0 = (x - m) * rs;
        float hn = fmaf(t0, sh_g[d], sh_b[d]);
        float ge = gelu_fast(hn);
        const float4* w = (const float4*)(sh_c2 + d * 16);
        float4 w0 = w[0], w1 = w[1], w2 = w[2], w3 = w[3];
        v[0]  = fmaf(ge, w0.x, v[0]);  v[1]  = fmaf(ge, w0.y, v[1]);
        v[2]  = fmaf(ge, w0.z, v[2]);  v[3]  = fmaf(ge, w0.w, v[3]);
        v[4]  = fmaf(ge, w1.x, v[4]);  v[5]  = fmaf(ge, w1.y, v[5]);
        v[6]  = fmaf(ge, w1.z, v[6]);  v[7]  = fmaf(ge, w1.w, v[7]);
        v[8]  = fmaf(ge, w2.x, v[8]);  v[9]  = fmaf(ge, w2.y, v[9]);
        v[10] = fmaf(ge, w2.z, v[10]); v[11] = fmaf(ge, w2.w, v[11]);
        v[12] = fmaf(ge, w3.x, v[12]); v[13] = fmaf(ge, w3.y, v[13]);
        v[14] = fmaf(ge, w3.z, v[14]); v[15] = fmaf(ge, w3.w, v[15]);
    }

    float* orow = out + ((size_t)i * NENT + j) * 18 + 1;
    #pragma unroll
    for (int t = 0; t < 16; t++) orow[t] = v[t] + sh_cb2v[t];
}

// ---------------------------------------------------------------------------
// Greedy quota filter. New: monotone 128-item skip-ahead for the tail.
// ---------------------------------------------------------------------------
__global__ void __launch_bounds__(1024) greedy_kernel(
    const unsigned long long* __restrict__ keys_s, float* __restrict__ selout)
{
    __shared__ unsigned long long buf[2][GW];
    __shared__ int counts[NENT];
    __shared__ unsigned em[NENT];
    __shared__ int s_done;

    int tid = threadIdx.x;
    for (int e = tid; e < NENT; e += blockDim.x) { counts[e] = 0; em[e] = 0u; }
    if (tid == 0) s_done = 0;

    int total = g_ncand;
    if (total > PAD) total = PAD;

    for (int k = tid; k < GW; k += blockDim.x) buf[0][k] = keys_s[k];
    __syncthreads();

    const int NWIN = PAD / GW;
    for (int w = 0; w < NWIN; w++) {
        if (tid >= 32 && (w + 1) < NWIN) {
            for (int k = tid - 32; k < GW; k += (blockDim.x - 32)) {
                buf[(w + 1) & 1][k] = keys_s[(w + 1) * GW + k];
            }
        }
        if (tid < 32) {
            int lane = tid;
            unsigned lt = (1u << lane) - 1u;
            int base = w * GW;
            if (base >= total) {
                if (lane == 0) s_done = 1;
            } else {
                int limit = total - base; if (limit > GW) limit = GW;
                const unsigned long long* cur = buf[w & 1];
                for (int cb = 0; cb < GW; cb += 128) {
                    if (cb >= limit) break;
                    // monotone skip test: counts only grow, so if nothing is
                    // viable now in these 128 items, nothing ever will be.
                    int any = 0;
                    #pragma unroll
                    for (int r = 0; r < 4; r++) {
                        int idx = cb + r * 32 + lane;
                        if (idx < limit) {
                            unsigned long long kk = cur[idx];
                            unsigned pp = (~(unsigned)kk) & 0x3FFFFu;
                            if (counts[pp >> 9] < 5 && counts[pp & (NENT - 1)] < 5) any = 1;
                        }
                    }
                    if (__ballot_sync(0xffffffffu, any) == 0u) continue;

                    for (int r = 0; r < 4; r++) {
                        int c = cb + r * 32;
                        if (c >= limit) break;
                        int active = (c + lane) < limit;
                        unsigned long long k = active ? cur[c + lane] : 0ull;
                        unsigned pidx = active ? ((~(unsigned)k) & 0x3FFFFu) : 0u;
                        int s = pidx >> 9, t = pidx & (NENT - 1);
                        int cs = counts[s], ct = counts[t];
                        int pre = active && (cs < 5) && (ct < 5);
                        unsigned pm = __ballot_sync(0xffffffffu, pre);
                        int accepted = 0;
                        if (pm) {
                            if (pre) { atomicOr(&em[s], 1u << lane); atomicOr(&em[t], 1u << lane); }
                            __syncwarp();
                            unsigned Ms = 0u, Mt = 0u;
                            if (pre) { Ms = em[s]; Mt = em[t]; }
                            int ub_s = __popc(Ms & lt);
                            int ub_t = __popc(Mt & lt);
                            int sure = pre && (cs + ub_s < 5) && (ct + ub_t < 5);
                            unsigned smask = __ballot_sync(0xffffffffu, sure);
                            unsigned u = pm & ~smask;
                            accepted = sure;
                            if (u) {
                                int ok = 0;
                                int es = __popc(Ms & smask & lt);
                                int et = __popc(Mt & smask & lt);
                                unsigned uu = u;
                                while (uu) {
                                    int l = __ffs(uu) - 1;
                                    int okl_local = ((cs + es) < 5) && ((ct + et) < 5);
                                    int okl = __shfl_sync(0xffffffffu, okl_local, l);
                                    int sl  = __shfl_sync(0xffffffffu, s, l);
                                    int tl  = __shfl_sync(0xffffffffu, t, l);
                                    if (okl) {
                                        es += (sl == s) + (tl == s);
                                        et += (sl == t) + (tl == t);
                                        if (lane == l) ok = 1;
                                    }
                                    uu &= uu - 1;
                                }
                                accepted |= ok;
                            }
                            if (accepted) {
                                atomicAdd(&counts[s], 1);
                                atomicAdd(&counts[t], 1);
                                selout[pidx] = 1.0f;
                            }
                            __syncwarp();
                            if (pre) { em[s] = 0u; em[t] = 0u; }
                            __syncwarp();
                        }
                    }
                }
                if (lane == 0 && base + GW >= total) s_done = 1;
            }
        }
        __syncthreads();
        if (s_done) break;
    }
}

// ---------------------------------------------------------------------------
extern "C" void kernel_launch(void* const* d_in, const int* in_sizes, int n_in,
                              void* d_out, int out_size) {
    const float* E      = (const float*)d_in[0];
    const int*   ebatch = (const int*)d_in[1];
    const float* sW1 = (const float*)d_in[3];
    const float* sb1 = (const float*)d_in[4];
    const float* s_g = (const float*)d_in[5];
    const float* s_b = (const float*)d_in[6];
    const float* sW2 = (const float*)d_in[7];
    const float* sb2 = (const float*)d_in[8];
    const float* cW1 = (const float*)d_in[9];
    const float* cb1 = (const float*)d_in[10];
    const float* c_g = (const float*)d_in[11];
    const float* c_b = (const float*)d_in[12];
    const float* cW2 = (const float*)d_in[13];
    const float* cb2 = (const float*)d_in[14];
    const float* dW1 = (const float*)d_in[15];
    const float* db1 = (const float*)d_in[16];
    const float* dW2 = (const float*)d_in[17];
    const float* db2 = (const float*)d_in[18];

    float* out = (float*)d_out;
    float* selout = out + ((size_t)out_size - NN);

    // pairc halves occupy launch slots 4 AND 5 (profile lands on one of them).
    gemm6_kernel<<<dim3(HID / 64, NENT / 64, 6), 256>>>(E, sW1, cW1, dW1, sb1, cb1, db1); // 1
    prep_kernel<<<192, 256>>>();                                                          // 2
    dotc_kernel<<<dim3(NENT / 64, NENT / 64), 256>>>();                                   // 3
    pairc_kernel<<<dim3(NENT / 256, 256), 256>>>(cW2, cb2, c_g, c_b, out, 0);             // 4
    pairc_kernel<<<dim3(NENT / 256, 256), 256>>>(cW2, cb2, c_g, c_b, out, 256);           // 5
    clear_kernel<<<32, 256>>>();                                                          // 6

    int shbytes = (2 * TJ * 256 + 2 * 256) * 4 + 16 * 4;
    cudaFuncSetAttribute(paira_kernel, cudaFuncAttributeMaxDynamicSharedMemorySize, shbytes);
    paira_kernel<<<dim3(NENT / TJ, NENT / TI), 256, shbytes>>>(                           // 7
        sW2, sb2, s_g, s_b, dW2, db2, ebatch, out, selout);

    void *pck, *pcks, *ptmp;
    cudaGetSymbolAddress(&pck,  g_ckeys);
    cudaGetSymbolAddress(&pcks, g_ckeys_s);
    cudaGetSymbolAddress(&ptmp, g_sort_tmp);
    size_t tb = 0;
    cub::DeviceRadixSort::SortKeysDescending(nullptr, tb,
        (const unsigned long long*)pck, (unsigned long long*)pcks, PAD, 0, 42, 0);
    if (tb > (size_t)(16u << 20)) tb = (size_t)(16u << 20);
    cub::DeviceRadixSort::SortKeysDescending(ptmp, tb,
        (const unsigned long long*)pck, (unsigned long long*)pcks, PAD, 0, 42, 0);

    greedy_kernel<<<1, 1024>>>((const unsigned long long*)pcks, selout);
}

// round 7
// speedup vs baseline: 1.0551x; 1.0551x over previous
#include <cuda_runtime.h>
#include <cuda_bf16.h>
#include <cub/cub.cuh>
#include <math.h>
#include <stdint.h>

#define NENT 512
#define DIM  768
#define HID  256
#define NT   16
#define NN   (NENT * NENT)
#define TI 8
#define TJ 16
#define PAD 65536           // candidate sort capacity
#define GW 2048             // greedy window (keys)

// ---------------- static device scratch (no allocs allowed) ----------------
__device__ float g_G[NENT * 6 * HID];   // [i][ s_i+b | c_i+b | d_i+b | s_j | c_j | d_j ]
__device__ float g_GTc[HID * NENT];     // transposed c_j block: [dim][entity]
__device__ float g_stats[NENT * 4];     // per entity: S1c, Q1c, S2c, Q2c
__device__ float g_dotc[NENT * NENT];   // hi_c . hj_c
__device__ unsigned long long g_ckeys[PAD];
__device__ unsigned long long g_ckeys_s[PAD];
__device__ int g_ncand;
__device__ unsigned char g_sort_tmp[16u << 20];

// ---------------------------------------------------------------------------
__global__ void clear_kernel() {
    int tid = blockIdx.x * blockDim.x + threadIdx.x;
    for (int k = tid; k < PAD; k += gridDim.x * blockDim.x) g_ckeys[k] = 0ull;
    if (tid == 0) g_ncand = 0;
}

// ---------------------------------------------------------------------------
// Kernel 1: six fused projections.
// ---------------------------------------------------------------------------
__global__ void __launch_bounds__(256) gemm6_kernel(
    const float* __restrict__ E,
    const float* __restrict__ sW1, const float* __restrict__ cW1, const float* __restrict__ dW1,
    const float* __restrict__ sb1, const float* __restrict__ cb1, const float* __restrict__ db1)
{
    __shared__ float  As[64][17];
    __shared__ float4 Bs[16 * 16];

    int z = blockIdx.z;
    const float* W = (z % 3 == 0) ? sW1 : (z % 3 == 1) ? cW1 : dW1;
    const float* bias = nullptr;
    if (z == 0) bias = sb1; else if (z == 1) bias = cb1; else if (z == 2) bias = db1;
    int rowoff  = (z < 3) ? 0 : DIM;
    int colbase = z * HID;

    int m0 = blockIdx.y * 64;
    int n0 = blockIdx.x * 64;
    int tid = threadIdx.x;
    int tx = tid & 15, ty = tid >> 4;
    int lrow = tid >> 2, lkq = tid & 3;
    int lk   = tid >> 4, lnq = tid & 15;

    float acc[4][4] = {};

    for (int k0 = 0; k0 < DIM; k0 += 16) {
        __syncthreads();
        float4 av = *(const float4*)(E + (size_t)(m0 + lrow) * DIM + k0 + lkq * 4);
        As[lrow][lkq * 4 + 0] = av.x;
        As[lrow][lkq * 4 + 1] = av.y;
        As[lrow][lkq * 4 + 2] = av.z;
        As[lrow][lkq * 4 + 3] = av.w;
        Bs[lk * 16 + lnq] = *(const float4*)(W + (size_t)(rowoff + k0 + lk) * HID + n0 + lnq * 4);
        __syncthreads();
        #pragma unroll
        for (int k = 0; k < 16; k++) {
            float a0 = As[ty * 4 + 0][k];
            float a1 = As[ty * 4 + 1][k];
            float a2 = As[ty * 4 + 2][k];
            float a3 = As[ty * 4 + 3][k];
            float4 b = Bs[k * 16 + tx];
            acc[0][0] = fmaf(a0, b.x, acc[0][0]); acc[0][1] = fmaf(a0, b.y, acc[0][1]);
            acc[0][2] = fmaf(a0, b.z, acc[0][2]); acc[0][3] = fmaf(a0, b.w, acc[0][3]);
            acc[1][0] = fmaf(a1, b.x, acc[1][0]); acc[1][1] = fmaf(a1, b.y, acc[1][1]);
            acc[1][2] = fmaf(a1, b.z, acc[1][2]); acc[1][3] = fmaf(a1, b.w, acc[1][3]);
            acc[2][0] = fmaf(a2, b.x, acc[2][0]); acc[2][1] = fmaf(a2, b.y, acc[2][1]);
            acc[2][2] = fmaf(a2, b.z, acc[2][2]); acc[2][3] = fmaf(a2, b.w, acc[2][3]);
            acc[3][0] = fmaf(a3, b.x, acc[3][0]); acc[3][1] = fmaf(a3, b.y, acc[3][1]);
            acc[3][2] = fmaf(a3, b.z, acc[3][2]); acc[3][3] = fmaf(a3, b.w, acc[3][3]);
        }
    }

    #pragma unroll
    for (int u = 0; u < 4; u++) {
        int gr = m0 + ty * 4 + u;
        int gc = n0 + tx * 4;
        float4 o;
        o.x = acc[u][0]; o.y = acc[u][1]; o.z = acc[u][2]; o.w = acc[u][3];
        if (bias) { o.x += bias[gc]; o.y += bias[gc + 1]; o.z += bias[gc + 2]; o.w += bias[gc + 3]; }
        *(float4*)(g_G + (size_t)gr * (6 * HID) + colbase + gc) = o;
    }
}

// ---------------------------------------------------------------------------
__device__ __forceinline__ float warpsum(float v) {
    v += __shfl_xor_sync(0xffffffffu, v, 16);
    v += __shfl_xor_sync(0xffffffffu, v, 8);
    v += __shfl_xor_sync(0xffffffffu, v, 4);
    v += __shfl_xor_sync(0xffffffffu, v, 2);
    v += __shfl_xor_sync(0xffffffffu, v, 1);
    return v;
}

// libdevice erff: FMA-polynomial, no MUFU — keep everywhere (R5 lesson).
__device__ __forceinline__ float gelu_exact(float x) {
    return 0.5f * x * (1.0f + erff(x * 0.70710678118654752440f));
}

// ---------------------------------------------------------------------------
// prep: transpose c_j into g_GTc + per-entity (sum, sumsq) stats.
// ---------------------------------------------------------------------------
__global__ void __launch_bounds__(256) prep_kernel() {
    int b = blockIdx.x;
    int tid = threadIdx.x;
    if (b < 128) {
        __shared__ float t[32][33];
        int e0 = (b & 15) * 32;
        int d0 = (b >> 4) * 32;
        int tx = tid & 31, ty = tid >> 5;
        #pragma unroll
        for (int r = 0; r < 4; r++) {
            int row = ty + r * 8;
            t[row][tx] = g_G[(size_t)(e0 + row) * 1536 + 1024 + d0 + tx];
        }
        __syncthreads();
        #pragma unroll
        for (int r = 0; r < 4; r++) {
            int row = ty + r * 8;
            g_GTc[(size_t)(d0 + row) * NENT + e0 + tx] = t[tx][row];
        }
    } else {
        int warp = tid >> 5, lane = tid & 31;
        int e = (b - 128) * 8 + warp;
        const float* gr = g_G + (size_t)e * 1536;
        float s1 = 0.f, q1 = 0.f, s2 = 0.f, q2 = 0.f;
        #pragma unroll
        for (int q = 0; q < 8; q++) {
            float a = gr[256 + lane * 8 + q];
            float c = gr[1024 + lane * 8 + q];
            s1 += a; q1 = fmaf(a, a, q1);
            s2 += c; q2 = fmaf(c, c, q2);
        }
        s1 = warpsum(s1); q1 = warpsum(q1); s2 = warpsum(s2); q2 = warpsum(q2);
        if (lane == 0) {
            float4 o; o.x = s1; o.y = q1; o.z = s2; o.w = q2;
            *(float4*)(g_stats + e * 4) = o;
        }
    }
}

// ---------------------------------------------------------------------------
// dotc[i][j] = hi_c[i] . hj_c[j]
// ---------------------------------------------------------------------------
__global__ void __launch_bounds__(256) dotc_kernel() {
    __shared__ float As[64][17];
    __shared__ float Bs2[64][17];

    int m0 = blockIdx.y * 64;
    int n0 = blockIdx.x * 64;
    int tid = threadIdx.x;
    int tx = tid & 15, ty = tid >> 4;
    int lrow = tid >> 2, lkq = tid & 3;

    float acc[4][4] = {};

    for (int k0 = 0; k0 < HID; k0 += 16) {
        __syncthreads();
        {
            float4 a = *(const float4*)(g_G + (size_t)(m0 + lrow) * 1536 + 256 + k0 + lkq * 4);
            As[lrow][lkq * 4 + 0] = a.x; As[lrow][lkq * 4 + 1] = a.y;
            As[lrow][lkq * 4 + 2] = a.z; As[lrow][lkq * 4 + 3] = a.w;
            float4 c = *(const float4*)(g_G + (size_t)(n0 + lrow) * 1536 + 1024 + k0 + lkq * 4);
            Bs2[lrow][lkq * 4 + 0] = c.x; Bs2[lrow][lkq * 4 + 1] = c.y;
            Bs2[lrow][lkq * 4 + 2] = c.z; Bs2[lrow][lkq * 4 + 3] = c.w;
        }
        __syncthreads();
        #pragma unroll
        for (int k = 0; k < 16; k++) {
            float a0 = As[ty * 4 + 0][k], a1 = As[ty * 4 + 1][k];
            float a2 = As[ty * 4 + 2][k], a3 = As[ty * 4 + 3][k];
            float b0 = Bs2[tx * 4 + 0][k], b1 = Bs2[tx * 4 + 1][k];
            float b2 = Bs2[tx * 4 + 2][k], b3 = Bs2[tx * 4 + 3][k];
            acc[0][0] = fmaf(a0, b0, acc[0][0]); acc[0][1] = fmaf(a0, b1, acc[0][1]);
            acc[0][2] = fmaf(a0, b2, acc[0][2]); acc[0][3] = fmaf(a0, b3, acc[0][3]);
            acc[1][0] = fmaf(a1, b0, acc[1][0]); acc[1][1] = fmaf(a1, b1, acc[1][1]);
            acc[1][2] = fmaf(a1, b2, acc[1][2]); acc[1][3] = fmaf(a1, b3, acc[1][3]);
            acc[2][0] = fmaf(a2, b0, acc[2][0]); acc[2][1] = fmaf(a2, b1, acc[2][1]);
            acc[2][2] = fmaf(a2, b2, acc[2][2]); acc[2][3] = fmaf(a2, b3, acc[2][3]);
            acc[3][0] = fmaf(a3, b0, acc[3][0]); acc[3][1] = fmaf(a3, b1, acc[3][1]);
            acc[3][2] = fmaf(a3, b2, acc[3][2]); acc[3][3] = fmaf(a3, b3, acc[3][3]);
        }
    }
    #pragma unroll
    for (int u = 0; u < 4; u++) {
        float4 o; o.x = acc[u][0]; o.y = acc[u][1]; o.z = acc[u][2]; o.w = acc[u][3];
        *(float4*)(g_dotc + (size_t)(m0 + ty * 4 + u) * NENT + n0 + tx * 4) = o;
    }
}

// ---------------------------------------------------------------------------
// pair_c: classifier head, thread-per-pair, GTc staged via DYNAMIC shared
// (52 KB > 48 KB static limit — R6 compile failure fix).
// Layout: [0,8192) sh_x | [8192,12288) sh_c2 | [12288,12800) sh_gb |
//         [12800,13056) sh_hic | [13056,13072) sh_cb2v      (floats)
// ---------------------------------------------------------------------------
#define PAIRC_SMEM ((32 * 256 + 256 * 16 + 2 * 256 + 256 + 16) * 4)

__global__ void __launch_bounds__(256) pairc_kernel(
    const float* __restrict__ cW2, const float* __restrict__ cb2,
    const float* __restrict__ c_g, const float* __restrict__ c_b,
    float* __restrict__ out)
{
    extern __shared__ float shc[];
    float*  sh_x    = shc;                    // [32][256]
    float*  sh_c2   = shc + 32 * 256;         // [256][16]
    float2* sh_gb   = (float2*)(shc + 32 * 256 + 256 * 16);   // [256]
    float*  sh_hic  = shc + 32 * 256 + 256 * 16 + 2 * 256;    // [256]
    float*  sh_cb2v = sh_hic + 256;           // [16]

    int tid = threadIdx.x;
    int i = blockIdx.y;
    int j0 = blockIdx.x * 256;
    int j = j0 + tid;

    sh_hic[tid] = g_G[(size_t)i * 1536 + 256 + tid];
    sh_gb[tid] = make_float2(c_g[tid], c_b[tid]);
    for (int k = tid; k < 1024; k += 256)
        ((float4*)sh_c2)[k] = ((const float4*)cW2)[k];
    if (tid < 16) sh_cb2v[tid] = cb2[tid];
    __syncthreads();

    const float inv256 = 1.0f / 256.0f;
    float4 stj = *(const float4*)(g_stats + j * 4);
    float S1 = g_stats[i * 4 + 0];
    float Q1 = g_stats[i * 4 + 1];
    float dot = g_dotc[(size_t)i * NENT + j];
    float m = (S1 + stj.z) * inv256;
    float var = fmaf(-m, m, (Q1 + 2.0f * dot + stj.w) * inv256);
    float rs = rsqrtf(var + 1e-5f);

    float v[16];
    #pragma unroll
    for (int t = 0; t < 16; t++) v[t] = 0.f;

    for (int c = 0; c < 8; c++) {
        // stage chunk: 32 d-rows x 256 j, coalesced float4, MLP=8, hic folded
        #pragma unroll
        for (int q = 0; q < 8; q++) {
            int f = q * 256 + tid;            // [0, 2048) float4 index
            int dl = f >> 6;                  // row within chunk
            int c4 = f & 63;                  // float4 column
            int d = c * 32 + dl;
            float4 g4 = *(const float4*)(g_GTc + (size_t)d * NENT + j0 + c4 * 4);
            float hic = sh_hic[d];
            g4.x += hic; g4.y += hic; g4.z += hic; g4.w += hic;
            *(float4*)(sh_x + dl * 256 + c4 * 4) = g4;
        }
        __syncthreads();

        #pragma unroll
        for (int dl = 0; dl < 32; dl++) {
            int d = c * 32 + dl;
            float x = sh_x[dl * 256 + tid];
            float2 gb = sh_gb[d];
            float hn = fmaf((x - m) * rs, gb.x, gb.y);
            float ge = gelu_exact(hn);
            const float4* w = (const float4*)(sh_c2 + d * 16);
            float4 w0 = w[0], w1 = w[1], w2 = w[2], w3 = w[3];
            v[0]  = fmaf(ge, w0.x, v[0]);  v[1]  = fmaf(ge, w0.y, v[1]);
            v[2]  = fmaf(ge, w0.z, v[2]);  v[3]  = fmaf(ge, w0.w, v[3]);
            v[4]  = fmaf(ge, w1.x, v[4]);  v[5]  = fmaf(ge, w1.y, v[5]);
            v[6]  = fmaf(ge, w1.z, v[6]);  v[7]  = fmaf(ge, w1.w, v[7]);
            v[8]  = fmaf(ge, w2.x, v[8]);  v[9]  = fmaf(ge, w2.y, v[9]);
            v[10] = fmaf(ge, w2.z, v[10]); v[11] = fmaf(ge, w2.w, v[11]);
            v[12] = fmaf(ge, w3.x, v[12]); v[13] = fmaf(ge, w3.y, v[13]);
            v[14] = fmaf(ge, w3.z, v[14]); v[15] = fmaf(ge, w3.w, v[15]);
        }
        __syncthreads();
    }

    float* orow = out + ((size_t)i * NENT + j) * 18 + 1;
    #pragma unroll
    for (int t = 0; t < 16; t++) orow[t] = v[t] + sh_cb2v[t];
}

// ---------------------------------------------------------------------------
// pair_a: s + d heads, all-exact math (R4 configuration: measured 214.9us).
// ---------------------------------------------------------------------------
__global__ void __launch_bounds__(256) paira_kernel(
    const float* __restrict__ sW2, const float* __restrict__ sb2,
    const float* __restrict__ s_g, const float* __restrict__ s_b,
    const float* __restrict__ dW2, const float* __restrict__ db2,
    const int* __restrict__ ebatch,
    float* __restrict__ out, float* __restrict__ selout)
{
    extern __shared__ float sh[];
    float* sh_hj  = sh;                       // [2][TJ][256]  (s_j, d_j)
    float* sh_sg  = sh + 2 * TJ * 256;        // 256
    float* sh_sb  = sh_sg + 256;
    int*   sh_jb  = (int*)(sh_sb + 256);      // 16

    int i0 = blockIdx.y * TI, j0 = blockIdx.x * TJ;
    int tid = threadIdx.x, warp = tid >> 5, lane = tid & 31;

    for (int v = tid; v < 2 * TJ * 64; v += 256) {
        int h = v / (TJ * 64); int rem = v % (TJ * 64);
        int jj = rem / 64; int c4 = rem % 64;
        float4 val = *(const float4*)(g_G + (size_t)(j0 + jj) * 1536 + (3 + 2 * h) * 256 + c4 * 4);
        *(float4*)(sh_hj + ((h * TJ + jj) * 256) + c4 * 4) = val;
    }
    { int c = tid; sh_sg[c] = s_g[c]; sh_sb[c] = s_b[c]; }
    if (tid < 16) sh_jb[tid] = ebatch[j0 + tid];
    __syncthreads();

    int i = i0 + warp;
    int d0 = lane * 8;

    float his[8], hid_[8];
    {
        const float* gr = g_G + (size_t)i * 1536;
        #pragma unroll
        for (int q = 0; q < 8; q++) {
            his[q]  = gr[d0 + q];
            hid_[q] = gr[512 + d0 + q];
        }
    }
    float s2[8], d2v[8];
    #pragma unroll
    for (int q = 0; q < 8; q++) { s2[q] = sW2[d0 + q]; d2v[q] = dW2[d0 + q]; }

    float sbias2 = sb2[0], dbias2 = db2[0];
    int bi = ebatch[i];
    const float inv256 = 1.0f / 256.0f;

    for (int jj = 0; jj < TJ; jj++) {
        int j = j0 + jj;
        float x[8];

        // -------- s head: BIT-IDENTICAL sequence (score path) --------
        const float* hj = sh_hj + (0 * TJ + jj) * 256 + d0;
        float ps = 0.f;
        #pragma unroll
        for (int q = 0; q < 8; q++) { x[q] = his[q] + hj[q]; ps += x[q]; }
        float m = warpsum(ps) * inv256;
        float pv = 0.f;
        #pragma unroll
        for (int q = 0; q < 8; q++) { float dd = x[q] - m; pv = fmaf(dd, dd, pv); }
        float rs = rsqrtf(warpsum(pv) * inv256 + 1e-5f);
        float acc = 0.f;
        #pragma unroll
        for (int q = 0; q < 8; q++) {
            float hn = (x[q] - m) * rs * sh_sg[d0 + q] + sh_sb[d0 + q];
            acc = fmaf(gelu_exact(hn), s2[q], acc);
        }
        acc = warpsum(acc);
        float score = 1.0f / (1.0f + expf(-(acc + sbias2)));

        // -------- d head --------
        const float* hjd = sh_hj + (1 * TJ + jj) * 256 + d0;
        float acc2 = 0.f;
        #pragma unroll
        for (int q = 0; q < 8; q++) {
            float xx = hid_[q] + hjd[q];
            acc2 = fmaf(gelu_exact(xx), d2v[q], acc2);
        }
        acc2 = warpsum(acc2);
        float dir = 1.0f / (1.0f + expf(-(acc2 + dbias2)));

        if (lane == 0) {
            size_t pidx = (size_t)i * NENT + j;
            float* orow = out + pidx * 18;
            orow[0]  = score;
            orow[17] = dir;
            selout[pidx] = 0.0f;
            int cand = (bi == sh_jb[jj]) && (i != j) && (score >= 0.5f);
            if (cand) {
                int pos = atomicAdd(&g_ncand, 1);
                if (pos < PAD) {
                    unsigned bits = __float_as_uint(score);
                    unsigned long long key =
                        ((unsigned long long)(bits - 0x3F000000u) << 18) |
                        (unsigned long long)((~(unsigned)pidx) & 0x3FFFFu);
                    g_ckeys[pos] = key;
                }
            }
        }
    }
}

// ---------------------------------------------------------------------------
// Greedy quota filter with monotone 128-item skip-ahead.
// ---------------------------------------------------------------------------
__global__ void __launch_bounds__(1024) greedy_kernel(
    const unsigned long long* __restrict__ keys_s, float* __restrict__ selout)
{
    __shared__ unsigned long long buf[2][GW];
    __shared__ int counts[NENT];
    __shared__ unsigned em[NENT];
    __shared__ int s_done;

    int tid = threadIdx.x;
    for (int e = tid; e < NENT; e += blockDim.x) { counts[e] = 0; em[e] = 0u; }
    if (tid == 0) s_done = 0;

    int total = g_ncand;
    if (total > PAD) total = PAD;

    for (int k = tid; k < GW; k += blockDim.x) buf[0][k] = keys_s[k];
    __syncthreads();

    const int NWIN = PAD / GW;
    for (int w = 0; w < NWIN; w++) {
        if (tid >= 32 && (w + 1) < NWIN) {
            for (int k = tid - 32; k < GW; k += (blockDim.x - 32)) {
                buf[(w + 1) & 1][k] = keys_s[(w + 1) * GW + k];
            }
        }
        if (tid < 32) {
            int lane = tid;
            unsigned lt = (1u << lane) - 1u;
            int base = w * GW;
            if (base >= total) {
                if (lane == 0) s_done = 1;
            } else {
                int limit = total - base; if (limit > GW) limit = GW;
                const unsigned long long* cur = buf[w & 1];
                for (int cb = 0; cb < GW; cb += 128) {
                    if (cb >= limit) break;
                    int any = 0;
                    #pragma unroll
                    for (int r = 0; r < 4; r++) {
                        int idx = cb + r * 32 + lane;
                        if (idx < limit) {
                            unsigned long long kk = cur[idx];
                            unsigned pp = (~(unsigned)kk) & 0x3FFFFu;
                            if (counts[pp >> 9] < 5 && counts[pp & (NENT - 1)] < 5) any = 1;
                        }
                    }
                    if (__ballot_sync(0xffffffffu, any) == 0u) continue;

                    for (int r = 0; r < 4; r++) {
                        int c = cb + r * 32;
                        if (c >= limit) break;
                        int active = (c + lane) < limit;
                        unsigned long long k = active ? cur[c + lane] : 0ull;
                        unsigned pidx = active ? ((~(unsigned)k) & 0x3FFFFu) : 0u;
                        int s = pidx >> 9, t = pidx & (NENT - 1);
                        int cs = counts[s], ct = counts[t];
                        int pre = active && (cs < 5) && (ct < 5);
                        unsigned pm = __ballot_sync(0xffffffffu, pre);
                        int accepted = 0;
                        if (pm) {
                            if (pre) { atomicOr(&em[s], 1u << lane); atomicOr(&em[t], 1u << lane); }
                            __syncwarp();
                            unsigned Ms = 0u, Mt = 0u;
                            if (pre) { Ms = em[s]; Mt = em[t]; }
                            int ub_s = __popc(Ms & lt);
                            int ub_t = __popc(Mt & lt);
                            int sure = pre && (cs + ub_s < 5) && (ct + ub_t < 5);
                            unsigned smask = __ballot_sync(0xffffffffu, sure);
                            unsigned u = pm & ~smask;
                            accepted = sure;
                            if (u) {
                                int ok = 0;
                                int es = __popc(Ms & smask & lt);
                                int et = __popc(Mt & smask & lt);
                                unsigned uu = u;
                                while (uu) {
                                    int l = __ffs(uu) - 1;
                                    int okl_local = ((cs + es) < 5) && ((ct + et) < 5);
                                    int okl = __shfl_sync(0xffffffffu, okl_local, l);
                                    int sl  = __shfl_sync(0xffffffffu, s, l);
                                    int tl  = __shfl_sync(0xffffffffu, t, l);
                                    if (okl) {
                                        es += (sl == s) + (tl == s);
                                        et += (sl == t) + (tl == t);
                                        if (lane == l) ok = 1;
                                    }
                                    uu &= uu - 1;
                                }
                                accepted |= ok;
                            }
                            if (accepted) {
                                atomicAdd(&counts[s], 1);
                                atomicAdd(&counts[t], 1);
                                selout[pidx] = 1.0f;
                            }
                            __syncwarp();
                            if (pre) { em[s] = 0u; em[t] = 0u; }
                            __syncwarp();
                        }
                    }
                }
                if (lane == 0 && base + GW >= total) s_done = 1;
            }
        }
        __syncthreads();
        if (s_done) break;
    }
}

// ---------------------------------------------------------------------------
extern "C" void kernel_launch(void* const* d_in, const int* in_sizes, int n_in,
                              void* d_out, int out_size) {
    const float* E      = (const float*)d_in[0];
    const int*   ebatch = (const int*)d_in[1];
    const float* sW1 = (const float*)d_in[3];
    const float* sb1 = (const float*)d_in[4];
    const float* s_g = (const float*)d_in[5];
    const float* s_b = (const float*)d_in[6];
    const float* sW2 = (const float*)d_in[7];
    const float* sb2 = (const float*)d_in[8];
    const float* cW1 = (const float*)d_in[9];
    const float* cb1 = (const float*)d_in[10];
    const float* c_g = (const float*)d_in[11];
    const float* c_b = (const float*)d_in[12];
    const float* cW2 = (const float*)d_in[13];
    const float* cb2 = (const float*)d_in[14];
    const float* dW1 = (const float*)d_in[15];
    const float* db1 = (const float*)d_in[16];
    const float* dW2 = (const float*)d_in[17];
    const float* db2 = (const float*)d_in[18];

    float* out = (float*)d_out;
    float* selout = out + ((size_t)out_size - NN);

    // slot #4 (profiled) = pairc — verify the staging fix
    gemm6_kernel<<<dim3(HID / 64, NENT / 64, 6), 256>>>(E, sW1, cW1, dW1, sb1, cb1, db1); // 1
    prep_kernel<<<192, 256>>>();                                                          // 2
    dotc_kernel<<<dim3(NENT / 64, NENT / 64), 256>>>();                                   // 3

    cudaFuncSetAttribute(pairc_kernel, cudaFuncAttributeMaxDynamicSharedMemorySize, PAIRC_SMEM);
    pairc_kernel<<<dim3(NENT / 256, NENT), 256, PAIRC_SMEM>>>(cW2, cb2, c_g, c_b, out);   // 4

    clear_kernel<<<32, 256>>>();                                                          // 5

    int shbytes = (2 * TJ * 256 + 2 * 256) * 4 + 16 * 4;
    cudaFuncSetAttribute(paira_kernel, cudaFuncAttributeMaxDynamicSharedMemorySize, shbytes);
    paira_kernel<<<dim3(NENT / TJ, NENT / TI), 256, shbytes>>>(                           // 6
        sW2, sb2, s_g, s_b, dW2, db2, ebatch, out, selout);

    void *pck, *pcks, *ptmp;
    cudaGetSymbolAddress(&pck,  g_ckeys);
    cudaGetSymbolAddress(&pcks, g_ckeys_s);
    cudaGetSymbolAddress(&ptmp, g_sort_tmp);
    size_t tb = 0;
    cub::DeviceRadixSort::SortKeysDescending(nullptr, tb,
        (const unsigned long long*)pck, (unsigned long long*)pcks, PAD, 0, 42, 0);
    if (tb > (size_t)(16u << 20)) tb = (size_t)(16u << 20);
    cub::DeviceRadixSort::SortKeysDescending(ptmp, tb,
        (const unsigned long long*)pck, (unsigned long long*)pcks, PAD, 0, 42, 0);

    greedy_kernel<<<1, 1024>>>((const unsigned long long*)pcks, selout);
}

// round 8
// speedup vs baseline: 1.4394x; 1.3642x over previous
#include <cuda_runtime.h>
#include <cuda_bf16.h>
#include <cub/cub.cuh>
#include <math.h>
#include <stdint.h>

#define NENT 512
#define DIM  768
#define HID  256
#define NT   16
#define NN   (NENT * NENT)
#define TI 8
#define TJ 16
#define PAD 65536           // >= max same-batch pairs (65024)

// ---------------- static device scratch (no allocs allowed) ----------------
__device__ float g_G[NENT * 6 * HID];   // [i][ s_i+b | c_i+b | d_i+b | s_j | c_j | d_j ]
__device__ float g_GTc[HID * NENT];     // transposed c_j block: [dim][entity]
__device__ float g_stats[NENT * 4];     // per entity: S1c, Q1c, S2c, Q2c
__device__ float g_dotc[NENT * NENT];   // hi_c . hj_c
__device__ unsigned long long g_ckeys[PAD];
__device__ unsigned long long g_ckeys_s[PAD];
__device__ int g_ncand;
__device__ int g_ncand_b[4];
__device__ unsigned char g_sort_tmp[16u << 20];

// ---------------------------------------------------------------------------
__global__ void clear_kernel() {
    int tid = blockIdx.x * blockDim.x + threadIdx.x;
    for (int k = tid; k < PAD; k += gridDim.x * blockDim.x) g_ckeys[k] = 0ull;
    if (tid == 0) { g_ncand = 0; g_ncand_b[0] = 0; g_ncand_b[1] = 0; g_ncand_b[2] = 0; g_ncand_b[3] = 0; }
}

__global__ void nop_kernel() {}

// ---------------------------------------------------------------------------
// Kernel 1: six fused projections.
// ---------------------------------------------------------------------------
__global__ void __launch_bounds__(256) gemm6_kernel(
    const float* __restrict__ E,
    const float* __restrict__ sW1, const float* __restrict__ cW1, const float* __restrict__ dW1,
    const float* __restrict__ sb1, const float* __restrict__ cb1, const float* __restrict__ db1)
{
    __shared__ float  As[64][17];
    __shared__ float4 Bs[16 * 16];

    int z = blockIdx.z;
    const float* W = (z % 3 == 0) ? sW1 : (z % 3 == 1) ? cW1 : dW1;
    const float* bias = nullptr;
    if (z == 0) bias = sb1; else if (z == 1) bias = cb1; else if (z == 2) bias = db1;
    int rowoff  = (z < 3) ? 0 : DIM;
    int colbase = z * HID;

    int m0 = blockIdx.y * 64;
    int n0 = blockIdx.x * 64;
    int tid = threadIdx.x;
    int tx = tid & 15, ty = tid >> 4;
    int lrow = tid >> 2, lkq = tid & 3;
    int lk   = tid >> 4, lnq = tid & 15;

    float acc[4][4] = {};

    for (int k0 = 0; k0 < DIM; k0 += 16) {
        __syncthreads();
        float4 av = *(const float4*)(E + (size_t)(m0 + lrow) * DIM + k0 + lkq * 4);
        As[lrow][lkq * 4 + 0] = av.x;
        As[lrow][lkq * 4 + 1] = av.y;
        As[lrow][lkq * 4 + 2] = av.z;
        As[lrow][lkq * 4 + 3] = av.w;
        Bs[lk * 16 + lnq] = *(const float4*)(W + (size_t)(rowoff + k0 + lk) * HID + n0 + lnq * 4);
        __syncthreads();
        #pragma unroll
        for (int k = 0; k < 16; k++) {
            float a0 = As[ty * 4 + 0][k];
            float a1 = As[ty * 4 + 1][k];
            float a2 = As[ty * 4 + 2][k];
            float a3 = As[ty * 4 + 3][k];
            float4 b = Bs[k * 16 + tx];
            acc[0][0] = fmaf(a0, b.x, acc[0][0]); acc[0][1] = fmaf(a0, b.y, acc[0][1]);
            acc[0][2] = fmaf(a0, b.z, acc[0][2]); acc[0][3] = fmaf(a0, b.w, acc[0][3]);
            acc[1][0] = fmaf(a1, b.x, acc[1][0]); acc[1][1] = fmaf(a1, b.y, acc[1][1]);
            acc[1][2] = fmaf(a1, b.z, acc[1][2]); acc[1][3] = fmaf(a1, b.w, acc[1][3]);
            acc[2][0] = fmaf(a2, b.x, acc[2][0]); acc[2][1] = fmaf(a2, b.y, acc[2][1]);
            acc[2][2] = fmaf(a2, b.z, acc[2][2]); acc[2][3] = fmaf(a2, b.w, acc[2][3]);
            acc[3][0] = fmaf(a3, b.x, acc[3][0]); acc[3][1] = fmaf(a3, b.y, acc[3][1]);
            acc[3][2] = fmaf(a3, b.z, acc[3][2]); acc[3][3] = fmaf(a3, b.w, acc[3][3]);
        }
    }

    #pragma unroll
    for (int u = 0; u < 4; u++) {
        int gr = m0 + ty * 4 + u;
        int gc = n0 + tx * 4;
        float4 o;
        o.x = acc[u][0]; o.y = acc[u][1]; o.z = acc[u][2]; o.w = acc[u][3];
        if (bias) { o.x += bias[gc]; o.y += bias[gc + 1]; o.z += bias[gc + 2]; o.w += bias[gc + 3]; }
        *(float4*)(g_G + (size_t)gr * (6 * HID) + colbase + gc) = o;
    }
}

// ---------------------------------------------------------------------------
__device__ __forceinline__ float warpsum(float v) {
    v += __shfl_xor_sync(0xffffffffu, v, 16);
    v += __shfl_xor_sync(0xffffffffu, v, 8);
    v += __shfl_xor_sync(0xffffffffu, v, 4);
    v += __shfl_xor_sync(0xffffffffu, v, 2);
    v += __shfl_xor_sync(0xffffffffu, v, 1);
    return v;
}

// libdevice erff: FMA-polynomial, no MUFU — keep everywhere (R5 lesson).
__device__ __forceinline__ float gelu_exact(float x) {
    return 0.5f * x * (1.0f + erff(x * 0.70710678118654752440f));
}

// ---------------------------------------------------------------------------
// prep: transpose c_j into g_GTc + per-entity (sum, sumsq) stats.
// ---------------------------------------------------------------------------
__global__ void __launch_bounds__(256) prep_kernel() {
    int b = blockIdx.x;
    int tid = threadIdx.x;
    if (b < 128) {
        __shared__ float t[32][33];
        int e0 = (b & 15) * 32;
        int d0 = (b >> 4) * 32;
        int tx = tid & 31, ty = tid >> 5;
        #pragma unroll
        for (int r = 0; r < 4; r++) {
            int row = ty + r * 8;
            t[row][tx] = g_G[(size_t)(e0 + row) * 1536 + 1024 + d0 + tx];
        }
        __syncthreads();
        #pragma unroll
        for (int r = 0; r < 4; r++) {
            int row = ty + r * 8;
            g_GTc[(size_t)(d0 + row) * NENT + e0 + tx] = t[tx][row];
        }
    } else {
        int warp = tid >> 5, lane = tid & 31;
        int e = (b - 128) * 8 + warp;
        const float* gr = g_G + (size_t)e * 1536;
        float s1 = 0.f, q1 = 0.f, s2 = 0.f, q2 = 0.f;
        #pragma unroll
        for (int q = 0; q < 8; q++) {
            float a = gr[256 + lane * 8 + q];
            float c = gr[1024 + lane * 8 + q];
            s1 += a; q1 = fmaf(a, a, q1);
            s2 += c; q2 = fmaf(c, c, q2);
        }
        s1 = warpsum(s1); q1 = warpsum(q1); s2 = warpsum(s2); q2 = warpsum(q2);
        if (lane == 0) {
            float4 o; o.x = s1; o.y = q1; o.z = s2; o.w = q2;
            *(float4*)(g_stats + e * 4) = o;
        }
    }
}

// ---------------------------------------------------------------------------
// dotc[i][j] = hi_c[i] . hj_c[j]
// ---------------------------------------------------------------------------
__global__ void __launch_bounds__(256) dotc_kernel() {
    __shared__ float As[64][17];
    __shared__ float Bs2[64][17];

    int m0 = blockIdx.y * 64;
    int n0 = blockIdx.x * 64;
    int tid = threadIdx.x;
    int tx = tid & 15, ty = tid >> 4;
    int lrow = tid >> 2, lkq = tid & 3;

    float acc[4][4] = {};

    for (int k0 = 0; k0 < HID; k0 += 16) {
        __syncthreads();
        {
            float4 a = *(const float4*)(g_G + (size_t)(m0 + lrow) * 1536 + 256 + k0 + lkq * 4);
            As[lrow][lkq * 4 + 0] = a.x; As[lrow][lkq * 4 + 1] = a.y;
            As[lrow][lkq * 4 + 2] = a.z; As[lrow][lkq * 4 + 3] = a.w;
            float4 c = *(const float4*)(g_G + (size_t)(n0 + lrow) * 1536 + 1024 + k0 + lkq * 4);
            Bs2[lrow][lkq * 4 + 0] = c.x; Bs2[lrow][lkq * 4 + 1] = c.y;
            Bs2[lrow][lkq * 4 + 2] = c.z; Bs2[lrow][lkq * 4 + 3] = c.w;
        }
        __syncthreads();
        #pragma unroll
        for (int k = 0; k < 16; k++) {
            float a0 = As[ty * 4 + 0][k], a1 = As[ty * 4 + 1][k];
            float a2 = As[ty * 4 + 2][k], a3 = As[ty * 4 + 3][k];
            float b0 = Bs2[tx * 4 + 0][k], b1 = Bs2[tx * 4 + 1][k];
            float b2 = Bs2[tx * 4 + 2][k], b3 = Bs2[tx * 4 + 3][k];
            acc[0][0] = fmaf(a0, b0, acc[0][0]); acc[0][1] = fmaf(a0, b1, acc[0][1]);
            acc[0][2] = fmaf(a0, b2, acc[0][2]); acc[0][3] = fmaf(a0, b3, acc[0][3]);
            acc[1][0] = fmaf(a1, b0, acc[1][0]); acc[1][1] = fmaf(a1, b1, acc[1][1]);
            acc[1][2] = fmaf(a1, b2, acc[1][2]); acc[1][3] = fmaf(a1, b3, acc[1][3]);
            acc[2][0] = fmaf(a2, b0, acc[2][0]); acc[2][1] = fmaf(a2, b1, acc[2][1]);
            acc[2][2] = fmaf(a2, b2, acc[2][2]); acc[2][3] = fmaf(a2, b3, acc[2][3]);
            acc[3][0] = fmaf(a3, b0, acc[3][0]); acc[3][1] = fmaf(a3, b1, acc[3][1]);
            acc[3][2] = fmaf(a3, b2, acc[3][2]); acc[3][3] = fmaf(a3, b3, acc[3][3]);
        }
    }
    #pragma unroll
    for (int u = 0; u < 4; u++) {
        float4 o; o.x = acc[u][0]; o.y = acc[u][1]; o.z = acc[u][2]; o.w = acc[u][3];
        *(float4*)(g_dotc + (size_t)(m0 + ty * 4 + u) * NENT + n0 + tx * 4) = o;
    }
}

// ---------------------------------------------------------------------------
// pair_c: classifier head, staged via dynamic shared (52 KB).
// ---------------------------------------------------------------------------
#define PAIRC_SMEM ((32 * 256 + 256 * 16 + 2 * 256 + 256 + 16) * 4)

__global__ void __launch_bounds__(256) pairc_kernel(
    const float* __restrict__ cW2, const float* __restrict__ cb2,
    const float* __restrict__ c_g, const float* __restrict__ c_b,
    float* __restrict__ out)
{
    extern __shared__ float shc[];
    float*  sh_x    = shc;                    // [32][256]
    float*  sh_c2   = shc + 32 * 256;         // [256][16]
    float2* sh_gb   = (float2*)(shc + 32 * 256 + 256 * 16);   // [256]
    float*  sh_hic  = shc + 32 * 256 + 256 * 16 + 2 * 256;    // [256]
    float*  sh_cb2v = sh_hic + 256;           // [16]

    int tid = threadIdx.x;
    int i = blockIdx.y;
    int j0 = blockIdx.x * 256;
    int j = j0 + tid;

    sh_hic[tid] = g_G[(size_t)i * 1536 + 256 + tid];
    sh_gb[tid] = make_float2(c_g[tid], c_b[tid]);
    for (int k = tid; k < 1024; k += 256)
        ((float4*)sh_c2)[k] = ((const float4*)cW2)[k];
    if (tid < 16) sh_cb2v[tid] = cb2[tid];
    __syncthreads();

    const float inv256 = 1.0f / 256.0f;
    float4 stj = *(const float4*)(g_stats + j * 4);
    float S1 = g_stats[i * 4 + 0];
    float Q1 = g_stats[i * 4 + 1];
    float dot = g_dotc[(size_t)i * NENT + j];
    float m = (S1 + stj.z) * inv256;
    float var = fmaf(-m, m, (Q1 + 2.0f * dot + stj.w) * inv256);
    float rs = rsqrtf(var + 1e-5f);

    float v[16];
    #pragma unroll
    for (int t = 0; t < 16; t++) v[t] = 0.f;

    for (int c = 0; c < 8; c++) {
        #pragma unroll
        for (int q = 0; q < 8; q++) {
            int f = q * 256 + tid;
            int dl = f >> 6;
            int c4 = f & 63;
            int d = c * 32 + dl;
            float4 g4 = *(const float4*)(g_GTc + (size_t)d * NENT + j0 + c4 * 4);
            float hic = sh_hic[d];
            g4.x += hic; g4.y += hic; g4.z += hic; g4.w += hic;
            *(float4*)(sh_x + dl * 256 + c4 * 4) = g4;
        }
        __syncthreads();

        #pragma unroll
        for (int dl = 0; dl < 32; dl++) {
            int d = c * 32 + dl;
            float x = sh_x[dl * 256 + tid];
            float2 gb = sh_gb[d];
            float hn = fmaf((x - m) * rs, gb.x, gb.y);
            float ge = gelu_exact(hn);
            const float4* w = (const float4*)(sh_c2 + d * 16);
            float4 w0 = w[0], w1 = w[1], w2 = w[2], w3 = w[3];
            v[0]  = fmaf(ge, w0.x, v[0]);  v[1]  = fmaf(ge, w0.y, v[1]);
            v[2]  = fmaf(ge, w0.z, v[2]);  v[3]  = fmaf(ge, w0.w, v[3]);
            v[4]  = fmaf(ge, w1.x, v[4]);  v[5]  = fmaf(ge, w1.y, v[5]);
            v[6]  = fmaf(ge, w1.z, v[6]);  v[7]  = fmaf(ge, w1.w, v[7]);
            v[8]  = fmaf(ge, w2.x, v[8]);  v[9]  = fmaf(ge, w2.y, v[9]);
            v[10] = fmaf(ge, w2.z, v[10]); v[11] = fmaf(ge, w2.w, v[11]);
            v[12] = fmaf(ge, w3.x, v[12]); v[13] = fmaf(ge, w3.y, v[13]);
            v[14] = fmaf(ge, w3.z, v[14]); v[15] = fmaf(ge, w3.w, v[15]);
        }
        __syncthreads();
    }

    float* orow = out + ((size_t)i * NENT + j) * 18 + 1;
    #pragma unroll
    for (int t = 0; t < 16; t++) orow[t] = v[t] + sh_cb2v[t];
}

// ---------------------------------------------------------------------------
// pair_a: s + d heads, all-exact math. Key now carries batch id in bits [42,44).
// ---------------------------------------------------------------------------
__global__ void __launch_bounds__(256) paira_kernel(
    const float* __restrict__ sW2, const float* __restrict__ sb2,
    const float* __restrict__ s_g, const float* __restrict__ s_b,
    const float* __restrict__ dW2, const float* __restrict__ db2,
    const int* __restrict__ ebatch,
    float* __restrict__ out, float* __restrict__ selout)
{
    extern __shared__ float sh[];
    float* sh_hj  = sh;                       // [2][TJ][256]  (s_j, d_j)
    float* sh_sg  = sh + 2 * TJ * 256;        // 256
    float* sh_sb  = sh_sg + 256;
    int*   sh_jb  = (int*)(sh_sb + 256);      // 16

    int i0 = blockIdx.y * TI, j0 = blockIdx.x * TJ;
    int tid = threadIdx.x, warp = tid >> 5, lane = tid & 31;

    for (int v = tid; v < 2 * TJ * 64; v += 256) {
        int h = v / (TJ * 64); int rem = v % (TJ * 64);
        int jj = rem / 64; int c4 = rem % 64;
        float4 val = *(const float4*)(g_G + (size_t)(j0 + jj) * 1536 + (3 + 2 * h) * 256 + c4 * 4);
        *(float4*)(sh_hj + ((h * TJ + jj) * 256) + c4 * 4) = val;
    }
    { int c = tid; sh_sg[c] = s_g[c]; sh_sb[c] = s_b[c]; }
    if (tid < 16) sh_jb[tid] = ebatch[j0 + tid];
    __syncthreads();

    int i = i0 + warp;
    int d0 = lane * 8;

    float his[8], hid_[8];
    {
        const float* gr = g_G + (size_t)i * 1536;
        #pragma unroll
        for (int q = 0; q < 8; q++) {
            his[q]  = gr[d0 + q];
            hid_[q] = gr[512 + d0 + q];
        }
    }
    float s2[8], d2v[8];
    #pragma unroll
    for (int q = 0; q < 8; q++) { s2[q] = sW2[d0 + q]; d2v[q] = dW2[d0 + q]; }

    float sbias2 = sb2[0], dbias2 = db2[0];
    int bi = ebatch[i];
    const float inv256 = 1.0f / 256.0f;

    for (int jj = 0; jj < TJ; jj++) {
        int j = j0 + jj;
        float x[8];

        // -------- s head: BIT-IDENTICAL sequence (score path) --------
        const float* hj = sh_hj + (0 * TJ + jj) * 256 + d0;
        float ps = 0.f;
        #pragma unroll
        for (int q = 0; q < 8; q++) { x[q] = his[q] + hj[q]; ps += x[q]; }
        float m = warpsum(ps) * inv256;
        float pv = 0.f;
        #pragma unroll
        for (int q = 0; q < 8; q++) { float dd = x[q] - m; pv = fmaf(dd, dd, pv); }
        float rs = rsqrtf(warpsum(pv) * inv256 + 1e-5f);
        float acc = 0.f;
        #pragma unroll
        for (int q = 0; q < 8; q++) {
            float hn = (x[q] - m) * rs * sh_sg[d0 + q] + sh_sb[d0 + q];
            acc = fmaf(gelu_exact(hn), s2[q], acc);
        }
        acc = warpsum(acc);
        float score = 1.0f / (1.0f + expf(-(acc + sbias2)));

        // -------- d head --------
        const float* hjd = sh_hj + (1 * TJ + jj) * 256 + d0;
        float acc2 = 0.f;
        #pragma unroll
        for (int q = 0; q < 8; q++) {
            float xx = hid_[q] + hjd[q];
            acc2 = fmaf(gelu_exact(xx), d2v[q], acc2);
        }
        acc2 = warpsum(acc2);
        float dir = 1.0f / (1.0f + expf(-(acc2 + dbias2)));

        if (lane == 0) {
            size_t pidx = (size_t)i * NENT + j;
            float* orow = out + pidx * 18;
            orow[0]  = score;
            orow[17] = dir;
            selout[pidx] = 0.0f;
            int cand = (bi == sh_jb[jj]) && (i != j) && (score >= 0.5f);
            if (cand) {
                int pos = atomicAdd(&g_ncand, 1);
                atomicAdd(&g_ncand_b[bi], 1);
                if (pos < PAD) {
                    unsigned bits = __float_as_uint(score);
                    unsigned long long key =
                        ((unsigned long long)(unsigned)bi << 42) |
                        ((unsigned long long)(bits - 0x3F000000u) << 18) |
                        (unsigned long long)((~(unsigned)pidx) & 0x3FFFFu);
                    g_ckeys[pos] = key;
                }
            }
        }
    }
}

// ---------------------------------------------------------------------------
// Greedy quota filter — batch-parallel: 4 warps, one per batch segment.
// Sorted 44-bit keys => segments [batch3 | batch2 | batch1 | batch0 | pads].
// Provably identical to global order: batches share no entities.
// ---------------------------------------------------------------------------
__global__ void __launch_bounds__(128) greedy_kernel(
    const unsigned long long* __restrict__ keys_s, float* __restrict__ selout)
{
    __shared__ int counts[NENT];
    __shared__ unsigned em[NENT];

    int tid = threadIdx.x;
    for (int e = tid; e < NENT; e += 128) { counts[e] = 0; em[e] = 0u; }
    __syncthreads();

    int warp = tid >> 5, lane = tid & 31;
    unsigned lt = (1u << lane) - 1u;

    int c3 = g_ncand_b[3], c2 = g_ncand_b[2], c1 = g_ncand_b[1], c0 = g_ncand_b[0];
    int b = 3 - warp;
    int start, len;
    if      (b == 3) { start = 0;            len = c3; }
    else if (b == 2) { start = c3;           len = c2; }
    else if (b == 1) { start = c3 + c2;      len = c1; }
    else             { start = c3 + c2 + c1; len = c0; }
    int end = start + len;
    if (end > PAD) end = PAD;

    // register prefetch of next chunk
    unsigned long long knext = (start + lane < end) ? __ldg(keys_s + start + lane) : 0ull;

    for (int base = start; base < end; base += 32) {
        unsigned long long k = knext;
        int nb = base + 32;
        knext = (nb + lane < end) ? __ldg(keys_s + nb + lane) : 0ull;

        int active = (base + lane) < end;
        unsigned pidx = (~(unsigned)k) & 0x3FFFFu;
        int s = pidx >> 9, t = pidx & (NENT - 1);
        int cs = counts[s], ct = counts[t];
        int pre = active && (cs < 5) && (ct < 5);
        unsigned pm = __ballot_sync(0xffffffffu, pre);
        if (!pm) continue;

        if (pre) { atomicOr(&em[s], 1u << lane); atomicOr(&em[t], 1u << lane); }
        __syncwarp();
        unsigned Ms = 0u, Mt = 0u;
        if (pre) { Ms = em[s]; Mt = em[t]; }
        int ub_s = __popc(Ms & lt);
        int ub_t = __popc(Mt & lt);
        int sure = pre && (cs + ub_s < 5) && (ct + ub_t < 5);
        unsigned smask = __ballot_sync(0xffffffffu, sure);
        unsigned u = pm & ~smask;
        int accepted = sure;
        if (u) {
            int ok = 0;
            int es = __popc(Ms & smask & lt);
            int et = __popc(Mt & smask & lt);
            unsigned uu = u;
            while (uu) {
                int l = __ffs(uu) - 1;
                int okl_local = ((cs + es) < 5) && ((ct + et) < 5);
                int okl = __shfl_sync(0xffffffffu, okl_local, l);
                int sl  = __shfl_sync(0xffffffffu, s, l);
                int tl  = __shfl_sync(0xffffffffu, t, l);
                if (okl) {
                    es += (sl == s) + (tl == s);
                    et += (sl == t) + (tl == t);
                    if (lane == l) ok = 1;
                }
                uu &= uu - 1;
            }
            accepted |= ok;
        }
        if (accepted) {
            atomicAdd(&counts[s], 1);
            atomicAdd(&counts[t], 1);
            selout[pidx] = 1.0f;
        }
        __syncwarp();
        if (pre) { em[s] = 0u; em[t] = 0u; }
        __syncwarp();
    }
}

// ---------------------------------------------------------------------------
extern "C" void kernel_launch(void* const* d_in, const int* in_sizes, int n_in,
                              void* d_out, int out_size) {
    const float* E      = (const float*)d_in[0];
    const int*   ebatch = (const int*)d_in[1];
    const float* sW1 = (const float*)d_in[3];
    const float* sb1 = (const float*)d_in[4];
    const float* s_g = (const float*)d_in[5];
    const float* s_b = (const float*)d_in[6];
    const float* sW2 = (const float*)d_in[7];
    const float* sb2 = (const float*)d_in[8];
    const float* cW1 = (const float*)d_in[9];
    const float* cb1 = (const float*)d_in[10];
    const float* c_g = (const float*)d_in[11];
    const float* c_b = (const float*)d_in[12];
    const float* cW2 = (const float*)d_in[13];
    const float* cb2 = (const float*)d_in[14];
    const float* dW1 = (const float*)d_in[15];
    const float* db1 = (const float*)d_in[16];
    const float* dW2 = (const float*)d_in[17];
    const float* db2 = (const float*)d_in[18];

    float* out = (float*)d_out;
    float* selout = out + ((size_t)out_size - NN);

    // slot #4 (profiled) = gemm6 this round — pin its cost
    clear_kernel<<<32, 256>>>();                                                          // 1
    nop_kernel<<<1, 1>>>();                                                               // 2
    nop_kernel<<<1, 1>>>();                                                               // 3
    gemm6_kernel<<<dim3(HID / 64, NENT / 64, 6), 256>>>(E, sW1, cW1, dW1, sb1, cb1, db1); // 4
    prep_kernel<<<192, 256>>>();                                                          // 5
    dotc_kernel<<<dim3(NENT / 64, NENT / 64), 256>>>();                                   // 6

    cudaFuncSetAttribute(pairc_kernel, cudaFuncAttributeMaxDynamicSharedMemorySize, PAIRC_SMEM);
    pairc_kernel<<<dim3(NENT / 256, NENT), 256, PAIRC_SMEM>>>(cW2, cb2, c_g, c_b, out);   // 7

    int shbytes = (2 * TJ * 256 + 2 * 256) * 4 + 16 * 4;
    cudaFuncSetAttribute(paira_kernel, cudaFuncAttributeMaxDynamicSharedMemorySize, shbytes);
    paira_kernel<<<dim3(NENT / TJ, NENT / TI), 256, shbytes>>>(                           // 8
        sW2, sb2, s_g, s_b, dW2, db2, ebatch, out, selout);

    void *pck, *pcks, *ptmp;
    cudaGetSymbolAddress(&pck,  g_ckeys);
    cudaGetSymbolAddress(&pcks, g_ckeys_s);
    cudaGetSymbolAddress(&ptmp, g_sort_tmp);
    size_t tb = 0;
    cub::DeviceRadixSort::SortKeysDescending(nullptr, tb,
        (const unsigned long long*)pck, (unsigned long long*)pcks, PAD, 0, 44, 0);
    if (tb > (size_t)(16u << 20)) tb = (size_t)(16u << 20);
    cub::DeviceRadixSort::SortKeysDescending(ptmp, tb,
        (const unsigned long long*)pck, (unsigned long long*)pcks, PAD, 0, 44, 0);

    greedy_kernel<<<1, 128>>>((const unsigned long long*)pcks, selout);
}